// round 4
// baseline (speedup 1.0000x reference)
#include <cuda_runtime.h>
#include <math.h>

#define HID   896
#define INTERD 2560
#define NEXP  16
#define TOPK  4
#define NTOK  2048
#define NSLOT (NTOK*TOPK)

// ---------------- packed f32x2 helpers (sm_103a) --------------------------------
__device__ __forceinline__ unsigned long long pack2_dup(float v) {
    unsigned long long r;
    asm("mov.b64 %0, {%1, %1};" : "=l"(r) : "f"(v));
    return r;
}
__device__ __forceinline__ void fma2(unsigned long long &c,
                                     unsigned long long a,
                                     unsigned long long b) {
    asm("fma.rn.f32x2 %0, %1, %2, %0;" : "+l"(c) : "l"(a), "l"(b));
}
__device__ __forceinline__ float2 unpack2(unsigned long long v) {
    float lo, hi;
    asm("mov.b64 {%0, %1}, %2;" : "=f"(lo), "=f"(hi) : "l"(v));
    return make_float2(lo, hi);
}

// ---------------- static device scratch (no runtime allocation) ----------------
__device__ float g_probsum[NEXP];
__device__ int   g_count[NEXP];
__device__ int   g_cursor[NEXP];
__device__ int   g_offset[NEXP];
__device__ int   g_topk_idx[NTOK][TOPK];
__device__ float g_topk_w[NTOK][TOPK];
__device__ int   g_slot_token[NSLOT];
__device__ int   g_token_slot[NTOK][TOPK];
__device__ float g_hshared[(size_t)NTOK * INTERD];   // ~21 MB
__device__ float g_oshared[(size_t)NTOK * HID];      // ~7 MB
__device__ float g_hrouted[(size_t)NSLOT * INTERD];  // ~84 MB
__device__ float g_drouted[(size_t)NSLOT * HID];     // ~29 MB

// ---------------- init: zero counters (runs every launch; graph-safe) ----------
__global__ void init_kernel() {
    int i = threadIdx.x;
    if (i < NEXP) {
        g_probsum[i] = 0.f;
        g_count[i]   = 0;
        g_cursor[i]  = 0;
    }
}

// ---------------- router: logits -> softmax -> top4 -> renorm ------------------
__global__ void router_kernel(const float* __restrict__ x,
                              const float* __restrict__ rw) {
    int t    = blockIdx.x;
    int lane = threadIdx.x;  // 32 threads
    const float* xr = x + (size_t)t * HID;
    __shared__ float logits[NEXP];

    for (int e = 0; e < NEXP; e++) {
        float s = 0.f;
        for (int k = lane; k < HID; k += 32) s += xr[k] * rw[k * NEXP + e];
        #pragma unroll
        for (int o = 16; o > 0; o >>= 1) s += __shfl_down_sync(0xffffffffu, s, o);
        if (lane == 0) logits[e] = s;
    }
    __syncwarp();
    if (lane != 0) return;

    float mx = -1e30f;
    #pragma unroll
    for (int e = 0; e < NEXP; e++) mx = fmaxf(mx, logits[e]);
    float p[NEXP]; float psum = 0.f;
    #pragma unroll
    for (int e = 0; e < NEXP; e++) { p[e] = __expf(logits[e] - mx); psum += p[e]; }
    float inv = 1.f / psum;
    #pragma unroll
    for (int e = 0; e < NEXP; e++) p[e] *= inv;

    // top-4 (ties -> lower index, matches jax top_k)
    bool used[NEXP] = {};
    int   idx[TOPK]; float val[TOPK]; float wsum = 0.f;
    #pragma unroll
    for (int k = 0; k < TOPK; k++) {
        int best = -1; float bv = -1.f;
        #pragma unroll
        for (int e = 0; e < NEXP; e++)
            if (!used[e] && p[e] > bv) { bv = p[e]; best = e; }
        used[best] = true; idx[k] = best; val[k] = bv; wsum += bv;
    }
    float winv = 1.f / (wsum + 1e-8f);
    #pragma unroll
    for (int k = 0; k < TOPK; k++) {
        g_topk_idx[t][k] = idx[k];
        g_topk_w[t][k]   = val[k] * winv;
        atomicAdd(&g_count[idx[k]], 1);
    }
    #pragma unroll
    for (int e = 0; e < NEXP; e++) atomicAdd(&g_probsum[e], p[e]);
}

// ---------------- exclusive scan of counts + balance loss ----------------------
__global__ void scan_loss_kernel(float* __restrict__ loss_out) {
    int off = 0; float loss = 0.f;
    for (int e = 0; e < NEXP; e++) {
        g_offset[e] = off; off += g_count[e];
        float f = (float)g_count[e] / (float)NTOK;
        float P = g_probsum[e] / (float)NTOK;
        loss += f * P;
    }
    *loss_out = (float)NEXP * loss;
}

// ---------------- per-expert token slot assignment ------------------------------
__global__ void assign_kernel() {
    int t = blockIdx.x * blockDim.x + threadIdx.x;
    if (t >= NTOK) return;
    #pragma unroll
    for (int k = 0; k < TOPK; k++) {
        int e = g_topk_idx[t][k];
        int pos = atomicAdd(&g_cursor[e], 1);
        int slot = g_offset[e] + pos;
        g_slot_token[slot]  = t;
        g_token_slot[t][k]  = slot;
    }
}

// ---------------- fused gate/up GEMM with SwiGLU epilogue -----------------------
// 128x64 block tile, 8x4 microtile, double-buffered smem, register prefetch.
__global__ void __launch_bounds__(256) gateup_gemm(
    const float* __restrict__ X,
    const float* __restrict__ WgBase,
    const float* __restrict__ WuBase,
    int routed)
{
    const int K = HID, N = INTERD;
    int e = blockIdx.z;
    int M; const int* rowmap; const float* Bg; const float* Bu; float* out;
    if (routed) {
        M = g_count[e];
        rowmap = g_slot_token + g_offset[e];
        Bg = WgBase + (size_t)e * K * N;
        Bu = WuBase + (size_t)e * K * N;
        out = g_hrouted + (size_t)g_offset[e] * N;
    } else {
        M = NTOK; rowmap = nullptr; Bg = WgBase; Bu = WuBase; out = g_hshared;
    }
    int m0 = blockIdx.y * 128;
    if (m0 >= M) return;
    int n0 = blockIdx.x * 64;

    __shared__ float As [2][16][128];
    __shared__ float Bgs[2][16][64];
    __shared__ float Bus[2][16][64];

    int tid  = threadIdx.x;
    // A tile: 512 float4 chunks; each thread loads chunk tid and tid+256.
    int ar0  = tid >> 2;             // row 0..63
    int ar1  = ar0 + 64;             // row 64..127
    int ak4  = (tid & 3) * 4;        // 0,4,8,12
    int brow = tid >> 4;             // 0..15
    int bcol = (tid & 15) * 4;       // 0..60
    int ty   = tid >> 4, tx = tid & 15;

    unsigned long long accg2[8][2] = {}, accu2[8][2] = {};

    int gm0 = m0 + ar0, gm1 = m0 + ar1;
    bool v0 = gm0 < M, v1 = gm1 < M;
    const float* Arow0 = nullptr; const float* Arow1 = nullptr;
    if (v0) { int r = rowmap ? rowmap[gm0] : gm0; Arow0 = X + (size_t)r * K; }
    if (v1) { int r = rowmap ? rowmap[gm1] : gm1; Arow1 = X + (size_t)r * K; }

    const float4 Z4 = make_float4(0.f, 0.f, 0.f, 0.f);

    // preload tile 0
    {
        float4 a0 = v0 ? *(const float4*)(Arow0 + ak4) : Z4;
        float4 a1 = v1 ? *(const float4*)(Arow1 + ak4) : Z4;
        As[0][ak4 + 0][ar0] = a0.x; As[0][ak4 + 1][ar0] = a0.y;
        As[0][ak4 + 2][ar0] = a0.z; As[0][ak4 + 3][ar0] = a0.w;
        As[0][ak4 + 0][ar1] = a1.x; As[0][ak4 + 1][ar1] = a1.y;
        As[0][ak4 + 2][ar1] = a1.z; As[0][ak4 + 3][ar1] = a1.w;
        *(float4*)&Bgs[0][brow][bcol] = *(const float4*)(Bg + (size_t)brow * N + n0 + bcol);
        *(float4*)&Bus[0][brow][bcol] = *(const float4*)(Bu + (size_t)brow * N + n0 + bcol);
    }
    __syncthreads();

    int cur = 0;
    for (int kt = 0; kt < K; kt += 16) {
        bool has_next = (kt + 16) < K;
        float4 a0n = Z4, a1n = Z4, bgn, bun;
        if (has_next) {
            if (v0) a0n = *(const float4*)(Arow0 + kt + 16 + ak4);
            if (v1) a1n = *(const float4*)(Arow1 + kt + 16 + ak4);
            bgn = *(const float4*)(Bg + (size_t)(kt + 16 + brow) * N + n0 + bcol);
            bun = *(const float4*)(Bu + (size_t)(kt + 16 + brow) * N + n0 + bcol);
        }
        #pragma unroll
        for (int k = 0; k < 16; k++) {
            float4 al = *(const float4*)&As[cur][k][ty * 8];
            float4 ah = *(const float4*)&As[cur][k][ty * 8 + 4];
            unsigned long long bg0 = *(const unsigned long long*)&Bgs[cur][k][tx * 4];
            unsigned long long bg1 = *(const unsigned long long*)&Bgs[cur][k][tx * 4 + 2];
            unsigned long long bu0 = *(const unsigned long long*)&Bus[cur][k][tx * 4];
            unsigned long long bu1 = *(const unsigned long long*)&Bus[cur][k][tx * 4 + 2];
            unsigned long long ap[8] = {
                pack2_dup(al.x), pack2_dup(al.y), pack2_dup(al.z), pack2_dup(al.w),
                pack2_dup(ah.x), pack2_dup(ah.y), pack2_dup(ah.z), pack2_dup(ah.w)};
            #pragma unroll
            for (int i = 0; i < 8; i++) {
                fma2(accg2[i][0], ap[i], bg0);
                fma2(accg2[i][1], ap[i], bg1);
                fma2(accu2[i][0], ap[i], bu0);
                fma2(accu2[i][1], ap[i], bu1);
            }
        }
        if (has_next) {
            int nb = cur ^ 1;
            As[nb][ak4 + 0][ar0] = a0n.x; As[nb][ak4 + 1][ar0] = a0n.y;
            As[nb][ak4 + 2][ar0] = a0n.z; As[nb][ak4 + 3][ar0] = a0n.w;
            As[nb][ak4 + 0][ar1] = a1n.x; As[nb][ak4 + 1][ar1] = a1n.y;
            As[nb][ak4 + 2][ar1] = a1n.z; As[nb][ak4 + 3][ar1] = a1n.w;
            *(float4*)&Bgs[nb][brow][bcol] = bgn;
            *(float4*)&Bus[nb][brow][bcol] = bun;
            __syncthreads();
            cur = nb;
        }
    }
    #pragma unroll
    for (int i = 0; i < 8; i++) {
        int m = m0 + ty * 8 + i;
        if (m >= M) continue;
        float* orow = out + (size_t)m * N + n0 + tx * 4;
        #pragma unroll
        for (int jp = 0; jp < 2; jp++) {
            float2 g2 = unpack2(accg2[i][jp]);
            float2 u2 = unpack2(accu2[i][jp]);
            orow[2 * jp + 0] = g2.x / (1.f + __expf(-g2.x)) * u2.x;  // silu(g)*u
            orow[2 * jp + 1] = g2.y / (1.f + __expf(-g2.y)) * u2.y;
        }
    }
}

// ---------------- down-projection GEMM (128x64 tile, 8x4 micro) -----------------
__global__ void __launch_bounds__(256) down_gemm(
    const float* __restrict__ WdBase, int routed)
{
    const int K = INTERD, N = HID;
    int e = blockIdx.z;
    int M; const float* A; const float* B; float* out;
    if (routed) {
        M = g_count[e];
        int off = g_offset[e];
        A = g_hrouted + (size_t)off * K;
        B = WdBase + (size_t)e * K * N;
        out = g_drouted + (size_t)off * N;
    } else {
        M = NTOK; A = g_hshared; B = WdBase; out = g_oshared;
    }
    int m0 = blockIdx.y * 128;
    if (m0 >= M) return;
    int n0 = blockIdx.x * 64;

    __shared__ float As[2][16][128];
    __shared__ float Bs[2][16][64];

    int tid  = threadIdx.x;
    int ar0  = tid >> 2;
    int ar1  = ar0 + 64;
    int ak4  = (tid & 3) * 4;
    int brow = tid >> 4;
    int bcol = (tid & 15) * 4;
    int ty   = tid >> 4, tx = tid & 15;

    unsigned long long acc2[8][2] = {};
    int gm0 = m0 + ar0, gm1 = m0 + ar1;
    bool v0 = gm0 < M, v1 = gm1 < M;
    const float* Arow0 = v0 ? (A + (size_t)gm0 * K) : nullptr;
    const float* Arow1 = v1 ? (A + (size_t)gm1 * K) : nullptr;
    const float4 Z4 = make_float4(0.f, 0.f, 0.f, 0.f);

    {
        float4 a0 = v0 ? *(const float4*)(Arow0 + ak4) : Z4;
        float4 a1 = v1 ? *(const float4*)(Arow1 + ak4) : Z4;
        As[0][ak4 + 0][ar0] = a0.x; As[0][ak4 + 1][ar0] = a0.y;
        As[0][ak4 + 2][ar0] = a0.z; As[0][ak4 + 3][ar0] = a0.w;
        As[0][ak4 + 0][ar1] = a1.x; As[0][ak4 + 1][ar1] = a1.y;
        As[0][ak4 + 2][ar1] = a1.z; As[0][ak4 + 3][ar1] = a1.w;
        *(float4*)&Bs[0][brow][bcol] = *(const float4*)(B + (size_t)brow * N + n0 + bcol);
    }
    __syncthreads();

    int cur = 0;
    for (int kt = 0; kt < K; kt += 16) {
        bool has_next = (kt + 16) < K;
        float4 a0n = Z4, a1n = Z4, bn;
        if (has_next) {
            if (v0) a0n = *(const float4*)(Arow0 + kt + 16 + ak4);
            if (v1) a1n = *(const float4*)(Arow1 + kt + 16 + ak4);
            bn = *(const float4*)(B + (size_t)(kt + 16 + brow) * N + n0 + bcol);
        }
        #pragma unroll
        for (int k = 0; k < 16; k++) {
            float4 al = *(const float4*)&As[cur][k][ty * 8];
            float4 ah = *(const float4*)&As[cur][k][ty * 8 + 4];
            unsigned long long b0 = *(const unsigned long long*)&Bs[cur][k][tx * 4];
            unsigned long long b1 = *(const unsigned long long*)&Bs[cur][k][tx * 4 + 2];
            unsigned long long ap[8] = {
                pack2_dup(al.x), pack2_dup(al.y), pack2_dup(al.z), pack2_dup(al.w),
                pack2_dup(ah.x), pack2_dup(ah.y), pack2_dup(ah.z), pack2_dup(ah.w)};
            #pragma unroll
            for (int i = 0; i < 8; i++) {
                fma2(acc2[i][0], ap[i], b0);
                fma2(acc2[i][1], ap[i], b1);
            }
        }
        if (has_next) {
            int nb = cur ^ 1;
            As[nb][ak4 + 0][ar0] = a0n.x; As[nb][ak4 + 1][ar0] = a0n.y;
            As[nb][ak4 + 2][ar0] = a0n.z; As[nb][ak4 + 3][ar0] = a0n.w;
            As[nb][ak4 + 0][ar1] = a1n.x; As[nb][ak4 + 1][ar1] = a1n.y;
            As[nb][ak4 + 2][ar1] = a1n.z; As[nb][ak4 + 3][ar1] = a1n.w;
            *(float4*)&Bs[nb][brow][bcol] = bn;
            __syncthreads();
            cur = nb;
        }
    }
    #pragma unroll
    for (int i = 0; i < 8; i++) {
        int m = m0 + ty * 8 + i;
        if (m >= M) continue;
        float* orow = out + (size_t)m * N + n0 + tx * 4;
        #pragma unroll
        for (int jp = 0; jp < 2; jp++) {
            float2 v2 = unpack2(acc2[i][jp]);
            orow[2 * jp + 0] = v2.x;
            orow[2 * jp + 1] = v2.y;
        }
    }
}

// ---------------- final combine: shared + weighted routed (deterministic) -------
__global__ void combine_kernel(float* __restrict__ outp) {
    const int NV = HID / 4;  // 224 float4 per token
    int i = blockIdx.x * blockDim.x + threadIdx.x;
    if (i >= NTOK * NV) return;
    int t = i / NV, dv = i - t * NV;
    const float4* sh4 = (const float4*)g_oshared;
    float4 v = sh4[i];
    #pragma unroll
    for (int k = 0; k < TOPK; k++) {
        int slot = g_token_slot[t][k];
        float w = g_topk_w[t][k];
        float4 r = *(const float4*)(g_drouted + (size_t)slot * HID + dv * 4);
        v.x = fmaf(w, r.x, v.x); v.y = fmaf(w, r.y, v.y);
        v.z = fmaf(w, r.z, v.z); v.w = fmaf(w, r.w, v.w);
    }
    ((float4*)outp)[i] = v;
}

// ---------------- launch ---------------------------------------------------------
extern "C" void kernel_launch(void* const* d_in, const int* in_sizes, int n_in,
                              void* d_out, int out_size) {
    const float* x  = (const float*)d_in[0];
    const float* rw = (const float*)d_in[1];
    const float* Wg = (const float*)d_in[2];
    const float* Wu = (const float*)d_in[3];
    const float* Wd = (const float*)d_in[4];
    const float* Sg = (const float*)d_in[5];
    const float* Su = (const float*)d_in[6];
    const float* Sd = (const float*)d_in[7];
    float* out = (float*)d_out;

    init_kernel<<<1, 32>>>();
    router_kernel<<<NTOK, 32>>>(x, rw);
    scan_loss_kernel<<<1, 1>>>(out + (out_size - 1));
    assign_kernel<<<NTOK / 256, 256>>>();

    // shared expert
    gateup_gemm<<<dim3(INTERD / 64, NTOK / 128, 1), 256>>>(x, Sg, Su, 0);
    // routed experts (grid.y sized for worst-case count; excess blocks exit)
    gateup_gemm<<<dim3(INTERD / 64, NTOK / 128, NEXP), 256>>>(x, Wg, Wu, 1);

    down_gemm<<<dim3(HID / 64, NTOK / 128, 1), 256>>>(Sd, 0);
    down_gemm<<<dim3(HID / 64, NTOK / 128, NEXP), 256>>>(Wd, 1);

    combine_kernel<<<(NTOK * (HID / 4) + 255) / 256, 256>>>(out);
}

// round 8
// speedup vs baseline: 1.3093x; 1.3093x over previous
#include <cuda_runtime.h>
#include <cuda_fp16.h>
#include <math.h>

#define HID   896
#define INTERD 2560
#define NEXP  16
#define TOPK  4
#define NTOK  2048
#define NSLOT (NTOK*TOPK)
#define KP    20   // padded k-row length (halves) for smem tiles

// ---------------- mma.sync m16n8k16 f16 -> f32 ---------------------------------
__device__ __forceinline__ void mma16816(float c[4], const unsigned a[4], const unsigned b[2]) {
    asm volatile(
        "mma.sync.aligned.m16n8k16.row.col.f32.f16.f16.f32 "
        "{%0,%1,%2,%3}, {%4,%5,%6,%7}, {%8,%9}, {%0,%1,%2,%3};\n"
        : "+f"(c[0]), "+f"(c[1]), "+f"(c[2]), "+f"(c[3])
        : "r"(a[0]), "r"(a[1]), "r"(a[2]), "r"(a[3]), "r"(b[0]), "r"(b[1]));
}

// split fp32 into fp16 hi + fp16 lo (2-term, ~22-bit effective mantissa)
__device__ __forceinline__ void split_store(float x, __half* ph, __half* pl) {
    __half h = __float2half_rn(x);
    *ph = h;
    *pl = __float2half_rn(x - __half2float(h));
}

__device__ __forceinline__ float silu_mul(float g, float u) {
    return g / (1.f + __expf(-g)) * u;
}

// ---------------- static device scratch ----------------------------------------
__device__ float g_probsum[NEXP];
__device__ int   g_count[NEXP];
__device__ int   g_cursor[NEXP];
__device__ int   g_offset[NEXP];
__device__ int   g_topk_idx[NTOK][TOPK];
__device__ float g_topk_w[NTOK][TOPK];
__device__ int   g_slot_token[NSLOT];
__device__ int   g_token_slot[NTOK][TOPK];
__device__ float g_hshared[(size_t)NTOK * INTERD];
__device__ float g_oshared[(size_t)NTOK * HID];
__device__ float g_hrouted[(size_t)NSLOT * INTERD];
__device__ float g_drouted[(size_t)NSLOT * HID];

// ---------------- init ----------------------------------------------------------
__global__ void init_kernel() {
    int i = threadIdx.x;
    if (i < NEXP) { g_probsum[i] = 0.f; g_count[i] = 0; g_cursor[i] = 0; }
}

// ---------------- router --------------------------------------------------------
__global__ void router_kernel(const float* __restrict__ x,
                              const float* __restrict__ rw) {
    int t = blockIdx.x, lane = threadIdx.x;
    const float* xr = x + (size_t)t * HID;
    __shared__ float logits[NEXP];
    for (int e = 0; e < NEXP; e++) {
        float s = 0.f;
        for (int k = lane; k < HID; k += 32) s += xr[k] * rw[k * NEXP + e];
        #pragma unroll
        for (int o = 16; o > 0; o >>= 1) s += __shfl_down_sync(0xffffffffu, s, o);
        if (lane == 0) logits[e] = s;
    }
    __syncwarp();
    if (lane != 0) return;
    float mx = -1e30f;
    #pragma unroll
    for (int e = 0; e < NEXP; e++) mx = fmaxf(mx, logits[e]);
    float p[NEXP]; float psum = 0.f;
    #pragma unroll
    for (int e = 0; e < NEXP; e++) { p[e] = __expf(logits[e] - mx); psum += p[e]; }
    float inv = 1.f / psum;
    #pragma unroll
    for (int e = 0; e < NEXP; e++) p[e] *= inv;
    bool used[NEXP] = {};
    int idx[TOPK]; float val[TOPK]; float wsum = 0.f;
    #pragma unroll
    for (int k = 0; k < TOPK; k++) {
        int best = -1; float bv = -1.f;
        #pragma unroll
        for (int e = 0; e < NEXP; e++)
            if (!used[e] && p[e] > bv) { bv = p[e]; best = e; }
        used[best] = true; idx[k] = best; val[k] = bv; wsum += bv;
    }
    float winv = 1.f / (wsum + 1e-8f);
    #pragma unroll
    for (int k = 0; k < TOPK; k++) {
        g_topk_idx[t][k] = idx[k];
        g_topk_w[t][k]   = val[k] * winv;
        atomicAdd(&g_count[idx[k]], 1);
    }
    #pragma unroll
    for (int e = 0; e < NEXP; e++) atomicAdd(&g_probsum[e], p[e]);
}

// ---------------- scan + loss ---------------------------------------------------
__global__ void scan_loss_kernel(float* __restrict__ loss_out) {
    int off = 0; float loss = 0.f;
    for (int e = 0; e < NEXP; e++) {
        g_offset[e] = off; off += g_count[e];
        float f = (float)g_count[e] / (float)NTOK;
        float P = g_probsum[e] / (float)NTOK;
        loss += f * P;
    }
    *loss_out = (float)NEXP * loss;
}

// ---------------- slot assignment ----------------------------------------------
__global__ void assign_kernel() {
    int t = blockIdx.x * blockDim.x + threadIdx.x;
    if (t >= NTOK) return;
    #pragma unroll
    for (int k = 0; k < TOPK; k++) {
        int e = g_topk_idx[t][k];
        int pos = atomicAdd(&g_cursor[e], 1);
        int slot = g_offset[e] + pos;
        g_slot_token[slot] = t;
        g_token_slot[t][k] = slot;
    }
}

// ---------------- gate/up GEMM: tensor-core, fp16 2-term split ------------------
// 128x64 tile, 8 warps (4m x 2n), warp tile 32x32 = 2 m-atoms x 4 n-atoms.
// grid.z: 0..NEXP-1 routed experts, NEXP = shared expert.
__global__ void __launch_bounds__(256) gateup_gemm(
    const float* __restrict__ X,
    const float* __restrict__ WgBase,
    const float* __restrict__ WuBase,
    const float* __restrict__ Sg,
    const float* __restrict__ Su)
{
    const int K = HID, N = INTERD;
    int e = blockIdx.z;
    int M; const int* rowmap; const float* Bg; const float* Bu; float* out;
    if (e < NEXP) {
        M = g_count[e];
        rowmap = g_slot_token + g_offset[e];
        Bg = WgBase + (size_t)e * K * N;
        Bu = WuBase + (size_t)e * K * N;
        out = g_hrouted + (size_t)g_offset[e] * N;
    } else {
        M = NTOK; rowmap = nullptr; Bg = Sg; Bu = Su; out = g_hshared;
    }
    int m0 = blockIdx.y * 128;
    if (m0 >= M) return;
    int n0 = blockIdx.x * 64;

    __shared__ __half Ah[2][128][KP], Al[2][128][KP];
    __shared__ __half Bgh[2][64][KP], Bgl[2][64][KP];
    __shared__ __half Buh[2][64][KP], Bul[2][64][KP];

    int tid  = threadIdx.x;
    int ar0  = tid >> 2, ar1 = ar0 + 64;
    int ak4  = (tid & 3) * 4;
    int brow = tid >> 4;            // k index 0..15
    int bcol = (tid & 15) * 4;      // n base 0..60
    int warp = tid >> 5;
    int wm   = warp & 3, wn = warp >> 2;
    int lane = tid & 31;
    int g    = lane >> 2, tig = lane & 3;

    float accg[2][4][4] = {}, accu[2][4][4] = {};

    int gm0 = m0 + ar0, gm1 = m0 + ar1;
    bool v0 = gm0 < M, v1 = gm1 < M;
    const float* Arow0 = nullptr; const float* Arow1 = nullptr;
    if (v0) { int r = rowmap ? rowmap[gm0] : gm0; Arow0 = X + (size_t)r * K; }
    if (v1) { int r = rowmap ? rowmap[gm1] : gm1; Arow1 = X + (size_t)r * K; }
    const float4 Z4 = make_float4(0.f, 0.f, 0.f, 0.f);

    // fill tile 0
    {
        float4 a0 = v0 ? *(const float4*)(Arow0 + ak4) : Z4;
        float4 a1 = v1 ? *(const float4*)(Arow1 + ak4) : Z4;
        split_store(a0.x, &Ah[0][ar0][ak4+0], &Al[0][ar0][ak4+0]);
        split_store(a0.y, &Ah[0][ar0][ak4+1], &Al[0][ar0][ak4+1]);
        split_store(a0.z, &Ah[0][ar0][ak4+2], &Al[0][ar0][ak4+2]);
        split_store(a0.w, &Ah[0][ar0][ak4+3], &Al[0][ar0][ak4+3]);
        split_store(a1.x, &Ah[0][ar1][ak4+0], &Al[0][ar1][ak4+0]);
        split_store(a1.y, &Ah[0][ar1][ak4+1], &Al[0][ar1][ak4+1]);
        split_store(a1.z, &Ah[0][ar1][ak4+2], &Al[0][ar1][ak4+2]);
        split_store(a1.w, &Ah[0][ar1][ak4+3], &Al[0][ar1][ak4+3]);
        float4 bg = *(const float4*)(Bg + (size_t)brow * N + n0 + bcol);
        float4 bu = *(const float4*)(Bu + (size_t)brow * N + n0 + bcol);
        split_store(bg.x, &Bgh[0][bcol+0][brow], &Bgl[0][bcol+0][brow]);
        split_store(bg.y, &Bgh[0][bcol+1][brow], &Bgl[0][bcol+1][brow]);
        split_store(bg.z, &Bgh[0][bcol+2][brow], &Bgl[0][bcol+2][brow]);
        split_store(bg.w, &Bgh[0][bcol+3][brow], &Bgl[0][bcol+3][brow]);
        split_store(bu.x, &Buh[0][bcol+0][brow], &Bul[0][bcol+0][brow]);
        split_store(bu.y, &Buh[0][bcol+1][brow], &Bul[0][bcol+1][brow]);
        split_store(bu.z, &Buh[0][bcol+2][brow], &Bul[0][bcol+2][brow]);
        split_store(bu.w, &Buh[0][bcol+3][brow], &Bul[0][bcol+3][brow]);
    }
    __syncthreads();

    int cur = 0;
    for (int kt = 0; kt < K; kt += 16) {
        bool has_next = (kt + 16) < K;
        float4 a0n = Z4, a1n = Z4, bgn, bun;
        if (has_next) {
            if (v0) a0n = *(const float4*)(Arow0 + kt + 16 + ak4);
            if (v1) a1n = *(const float4*)(Arow1 + kt + 16 + ak4);
            bgn = *(const float4*)(Bg + (size_t)(kt + 16 + brow) * N + n0 + bcol);
            bun = *(const float4*)(Bu + (size_t)(kt + 16 + brow) * N + n0 + bcol);
        }
        // A fragments
        unsigned ahf[2][4], alf[2][4];
        #pragma unroll
        for (int ma = 0; ma < 2; ma++) {
            int r = wm * 32 + ma * 16 + g;
            ahf[ma][0] = *(const unsigned*)&Ah[cur][r    ][2*tig    ];
            ahf[ma][1] = *(const unsigned*)&Ah[cur][r + 8][2*tig    ];
            ahf[ma][2] = *(const unsigned*)&Ah[cur][r    ][2*tig + 8];
            ahf[ma][3] = *(const unsigned*)&Ah[cur][r + 8][2*tig + 8];
            alf[ma][0] = *(const unsigned*)&Al[cur][r    ][2*tig    ];
            alf[ma][1] = *(const unsigned*)&Al[cur][r + 8][2*tig    ];
            alf[ma][2] = *(const unsigned*)&Al[cur][r    ][2*tig + 8];
            alf[ma][3] = *(const unsigned*)&Al[cur][r + 8][2*tig + 8];
        }
        #pragma unroll
        for (int na = 0; na < 4; na++) {
            int n = wn * 32 + na * 8 + g;
            unsigned bh[2], bl[2], uh[2], ul[2];
            bh[0] = *(const unsigned*)&Bgh[cur][n][2*tig    ];
            bh[1] = *(const unsigned*)&Bgh[cur][n][2*tig + 8];
            bl[0] = *(const unsigned*)&Bgl[cur][n][2*tig    ];
            bl[1] = *(const unsigned*)&Bgl[cur][n][2*tig + 8];
            uh[0] = *(const unsigned*)&Buh[cur][n][2*tig    ];
            uh[1] = *(const unsigned*)&Buh[cur][n][2*tig + 8];
            ul[0] = *(const unsigned*)&Bul[cur][n][2*tig    ];
            ul[1] = *(const unsigned*)&Bul[cur][n][2*tig + 8];
            #pragma unroll
            for (int ma = 0; ma < 2; ma++) {
                mma16816(accg[ma][na], ahf[ma], bh);
                mma16816(accg[ma][na], alf[ma], bh);
                mma16816(accg[ma][na], ahf[ma], bl);
                mma16816(accu[ma][na], ahf[ma], uh);
                mma16816(accu[ma][na], alf[ma], uh);
                mma16816(accu[ma][na], ahf[ma], ul);
            }
        }
        if (has_next) {
            int nb = cur ^ 1;
            split_store(a0n.x, &Ah[nb][ar0][ak4+0], &Al[nb][ar0][ak4+0]);
            split_store(a0n.y, &Ah[nb][ar0][ak4+1], &Al[nb][ar0][ak4+1]);
            split_store(a0n.z, &Ah[nb][ar0][ak4+2], &Al[nb][ar0][ak4+2]);
            split_store(a0n.w, &Ah[nb][ar0][ak4+3], &Al[nb][ar0][ak4+3]);
            split_store(a1n.x, &Ah[nb][ar1][ak4+0], &Al[nb][ar1][ak4+0]);
            split_store(a1n.y, &Ah[nb][ar1][ak4+1], &Al[nb][ar1][ak4+1]);
            split_store(a1n.z, &Ah[nb][ar1][ak4+2], &Al[nb][ar1][ak4+2]);
            split_store(a1n.w, &Ah[nb][ar1][ak4+3], &Al[nb][ar1][ak4+3]);
            split_store(bgn.x, &Bgh[nb][bcol+0][brow], &Bgl[nb][bcol+0][brow]);
            split_store(bgn.y, &Bgh[nb][bcol+1][brow], &Bgl[nb][bcol+1][brow]);
            split_store(bgn.z, &Bgh[nb][bcol+2][brow], &Bgl[nb][bcol+2][brow]);
            split_store(bgn.w, &Bgh[nb][bcol+3][brow], &Bgl[nb][bcol+3][brow]);
            split_store(bun.x, &Buh[nb][bcol+0][brow], &Bul[nb][bcol+0][brow]);
            split_store(bun.y, &Buh[nb][bcol+1][brow], &Bul[nb][bcol+1][brow]);
            split_store(bun.z, &Buh[nb][bcol+2][brow], &Bul[nb][bcol+2][brow]);
            split_store(bun.w, &Buh[nb][bcol+3][brow], &Bul[nb][bcol+3][brow]);
            __syncthreads();
            cur = nb;
        }
    }
    // epilogue: silu(g)*u
    #pragma unroll
    for (int ma = 0; ma < 2; ma++) {
        int r0 = m0 + wm * 32 + ma * 16 + g;
        int r1 = r0 + 8;
        #pragma unroll
        for (int na = 0; na < 4; na++) {
            int c = n0 + wn * 32 + na * 8 + 2 * tig;
            if (r0 < M) {
                float* o = out + (size_t)r0 * N + c;
                o[0] = silu_mul(accg[ma][na][0], accu[ma][na][0]);
                o[1] = silu_mul(accg[ma][na][1], accu[ma][na][1]);
            }
            if (r1 < M) {
                float* o = out + (size_t)r1 * N + c;
                o[0] = silu_mul(accg[ma][na][2], accu[ma][na][2]);
                o[1] = silu_mul(accg[ma][na][3], accu[ma][na][3]);
            }
        }
    }
}

// ---------------- down GEMM: tensor-core, fp16 2-term split ---------------------
__global__ void __launch_bounds__(256) down_gemm(
    const float* __restrict__ WdBase,
    const float* __restrict__ Sd)
{
    const int K = INTERD, N = HID;
    int e = blockIdx.z;
    int M; const float* A; const float* B; float* out;
    if (e < NEXP) {
        M = g_count[e];
        int off = g_offset[e];
        A = g_hrouted + (size_t)off * K;
        B = WdBase + (size_t)e * K * N;
        out = g_drouted + (size_t)off * N;
    } else {
        M = NTOK; A = g_hshared; B = Sd; out = g_oshared;
    }
    int m0 = blockIdx.y * 128;
    if (m0 >= M) return;
    int n0 = blockIdx.x * 64;

    __shared__ __half Ah[2][128][KP], Al[2][128][KP];
    __shared__ __half Bh[2][64][KP],  Bl[2][64][KP];

    int tid  = threadIdx.x;
    int ar0  = tid >> 2, ar1 = ar0 + 64;
    int ak4  = (tid & 3) * 4;
    int brow = tid >> 4;
    int bcol = (tid & 15) * 4;
    int warp = tid >> 5;
    int wm   = warp & 3, wn = warp >> 2;
    int lane = tid & 31;
    int g    = lane >> 2, tig = lane & 3;

    float acc[2][4][4] = {};
    int gm0 = m0 + ar0, gm1 = m0 + ar1;
    bool v0 = gm0 < M, v1 = gm1 < M;
    const float* Arow0 = v0 ? (A + (size_t)gm0 * K) : nullptr;
    const float* Arow1 = v1 ? (A + (size_t)gm1 * K) : nullptr;
    const float4 Z4 = make_float4(0.f, 0.f, 0.f, 0.f);

    {
        float4 a0 = v0 ? *(const float4*)(Arow0 + ak4) : Z4;
        float4 a1 = v1 ? *(const float4*)(Arow1 + ak4) : Z4;
        split_store(a0.x, &Ah[0][ar0][ak4+0], &Al[0][ar0][ak4+0]);
        split_store(a0.y, &Ah[0][ar0][ak4+1], &Al[0][ar0][ak4+1]);
        split_store(a0.z, &Ah[0][ar0][ak4+2], &Al[0][ar0][ak4+2]);
        split_store(a0.w, &Ah[0][ar0][ak4+3], &Al[0][ar0][ak4+3]);
        split_store(a1.x, &Ah[0][ar1][ak4+0], &Al[0][ar1][ak4+0]);
        split_store(a1.y, &Ah[0][ar1][ak4+1], &Al[0][ar1][ak4+1]);
        split_store(a1.z, &Ah[0][ar1][ak4+2], &Al[0][ar1][ak4+2]);
        split_store(a1.w, &Ah[0][ar1][ak4+3], &Al[0][ar1][ak4+3]);
        float4 bv = *(const float4*)(B + (size_t)brow * N + n0 + bcol);
        split_store(bv.x, &Bh[0][bcol+0][brow], &Bl[0][bcol+0][brow]);
        split_store(bv.y, &Bh[0][bcol+1][brow], &Bl[0][bcol+1][brow]);
        split_store(bv.z, &Bh[0][bcol+2][brow], &Bl[0][bcol+2][brow]);
        split_store(bv.w, &Bh[0][bcol+3][brow], &Bl[0][bcol+3][brow]);
    }
    __syncthreads();

    int cur = 0;
    for (int kt = 0; kt < K; kt += 16) {
        bool has_next = (kt + 16) < K;
        float4 a0n = Z4, a1n = Z4, bn;
        if (has_next) {
            if (v0) a0n = *(const float4*)(Arow0 + kt + 16 + ak4);
            if (v1) a1n = *(const float4*)(Arow1 + kt + 16 + ak4);
            bn = *(const float4*)(B + (size_t)(kt + 16 + brow) * N + n0 + bcol);
        }
        unsigned ahf[2][4], alf[2][4];
        #pragma unroll
        for (int ma = 0; ma < 2; ma++) {
            int r = wm * 32 + ma * 16 + g;
            ahf[ma][0] = *(const unsigned*)&Ah[cur][r    ][2*tig    ];
            ahf[ma][1] = *(const unsigned*)&Ah[cur][r + 8][2*tig    ];
            ahf[ma][2] = *(const unsigned*)&Ah[cur][r    ][2*tig + 8];
            ahf[ma][3] = *(const unsigned*)&Ah[cur][r + 8][2*tig + 8];
            alf[ma][0] = *(const unsigned*)&Al[cur][r    ][2*tig    ];
            alf[ma][1] = *(const unsigned*)&Al[cur][r + 8][2*tig    ];
            alf[ma][2] = *(const unsigned*)&Al[cur][r    ][2*tig + 8];
            alf[ma][3] = *(const unsigned*)&Al[cur][r + 8][2*tig + 8];
        }
        #pragma unroll
        for (int na = 0; na < 4; na++) {
            int n = wn * 32 + na * 8 + g;
            unsigned bh[2], bl[2];
            bh[0] = *(const unsigned*)&Bh[cur][n][2*tig    ];
            bh[1] = *(const unsigned*)&Bh[cur][n][2*tig + 8];
            bl[0] = *(const unsigned*)&Bl[cur][n][2*tig    ];
            bl[1] = *(const unsigned*)&Bl[cur][n][2*tig + 8];
            #pragma unroll
            for (int ma = 0; ma < 2; ma++) {
                mma16816(acc[ma][na], ahf[ma], bh);
                mma16816(acc[ma][na], alf[ma], bh);
                mma16816(acc[ma][na], ahf[ma], bl);
            }
        }
        if (has_next) {
            int nb = cur ^ 1;
            split_store(a0n.x, &Ah[nb][ar0][ak4+0], &Al[nb][ar0][ak4+0]);
            split_store(a0n.y, &Ah[nb][ar0][ak4+1], &Al[nb][ar0][ak4+1]);
            split_store(a0n.z, &Ah[nb][ar0][ak4+2], &Al[nb][ar0][ak4+2]);
            split_store(a0n.w, &Ah[nb][ar0][ak4+3], &Al[nb][ar0][ak4+3]);
            split_store(a1n.x, &Ah[nb][ar1][ak4+0], &Al[nb][ar1][ak4+0]);
            split_store(a1n.y, &Ah[nb][ar1][ak4+1], &Al[nb][ar1][ak4+1]);
            split_store(a1n.z, &Ah[nb][ar1][ak4+2], &Al[nb][ar1][ak4+2]);
            split_store(a1n.w, &Ah[nb][ar1][ak4+3], &Al[nb][ar1][ak4+3]);
            split_store(bn.x, &Bh[nb][bcol+0][brow], &Bl[nb][bcol+0][brow]);
            split_store(bn.y, &Bh[nb][bcol+1][brow], &Bl[nb][bcol+1][brow]);
            split_store(bn.z, &Bh[nb][bcol+2][brow], &Bl[nb][bcol+2][brow]);
            split_store(bn.w, &Bh[nb][bcol+3][brow], &Bl[nb][bcol+3][brow]);
            __syncthreads();
            cur = nb;
        }
    }
    #pragma unroll
    for (int ma = 0; ma < 2; ma++) {
        int r0 = m0 + wm * 32 + ma * 16 + g;
        int r1 = r0 + 8;
        #pragma unroll
        for (int na = 0; na < 4; na++) {
            int c = n0 + wn * 32 + na * 8 + 2 * tig;
            if (r0 < M) {
                float* o = out + (size_t)r0 * N + c;
                o[0] = acc[ma][na][0];
                o[1] = acc[ma][na][1];
            }
            if (r1 < M) {
                float* o = out + (size_t)r1 * N + c;
                o[0] = acc[ma][na][2];
                o[1] = acc[ma][na][3];
            }
        }
    }
}

// ---------------- final combine (deterministic) ---------------------------------
__global__ void combine_kernel(float* __restrict__ outp) {
    const int NV = HID / 4;
    int i = blockIdx.x * blockDim.x + threadIdx.x;
    if (i >= NTOK * NV) return;
    int t = i / NV, dv = i - t * NV;
    const float4* sh4 = (const float4*)g_oshared;
    float4 v = sh4[i];
    #pragma unroll
    for (int k = 0; k < TOPK; k++) {
        int slot = g_token_slot[t][k];
        float w = g_topk_w[t][k];
        float4 r = *(const float4*)(g_drouted + (size_t)slot * HID + dv * 4);
        v.x = fmaf(w, r.x, v.x); v.y = fmaf(w, r.y, v.y);
        v.z = fmaf(w, r.z, v.z); v.w = fmaf(w, r.w, v.w);
    }
    ((float4*)outp)[i] = v;
}

// ---------------- launch ---------------------------------------------------------
extern "C" void kernel_launch(void* const* d_in, const int* in_sizes, int n_in,
                              void* d_out, int out_size) {
    const float* x  = (const float*)d_in[0];
    const float* rw = (const float*)d_in[1];
    const float* Wg = (const float*)d_in[2];
    const float* Wu = (const float*)d_in[3];
    const float* Wd = (const float*)d_in[4];
    const float* Sg = (const float*)d_in[5];
    const float* Su = (const float*)d_in[6];
    const float* Sd = (const float*)d_in[7];
    float* out = (float*)d_out;

    init_kernel<<<1, 32>>>();
    router_kernel<<<NTOK, 32>>>(x, rw);
    scan_loss_kernel<<<1, 1>>>(out + (out_size - 1));
    assign_kernel<<<NTOK / 256, 256>>>();

    // z: 0..15 routed experts, 16 = shared expert (runs in same launch)
    gateup_gemm<<<dim3(INTERD / 64, NTOK / 128, NEXP + 1), 256>>>(x, Wg, Wu, Sg, Su);
    down_gemm<<<dim3(HID / 64, NTOK / 128, NEXP + 1), 256>>>(Wd, Sd);

    combine_kernel<<<(NTOK * (HID / 4) + 255) / 256, 256>>>(out);
}